// round 5
// baseline (speedup 1.0000x reference)
#include <cuda_runtime.h>
#include <cstdint>
#include <cstddef>

#define BB 128
#define NN 2048
#define HH 64
#define SS 64

typedef unsigned long long u64;

// ---------------- scratch (static device memory; no allocation) ----------------
__device__ __align__(256) float d_h0[(size_t)BB * HH * NN];   // 64 MB, [b][c][rank]
__device__ __align__(256) float d_h1[(size_t)BB * HH * NN];   // 64 MB
__device__ __align__(256) float d_agg0[BB * SS * HH];
__device__ __align__(256) float d_agg1[BB * SS * HH];
__device__ __align__(256) float d_agg2[BB * SS * HH];
__device__ __align__(256) float d_aggW[BB * SS * HH];         // bias + agg@W_bot, per layer
__device__ int            d_perm[BB * NN];
__device__ int            d_cs[BB * NN];                      // sorted cluster ids

// ---------------- f32x2 packed fp32 helpers (bit-exact IEEE fma on both halves) ----------------
__device__ __forceinline__ u64 pack2f(float lo, float hi) {
    u64 r; asm("mov.b64 %0, {%1,%2};" : "=l"(r) : "f"(lo), "f"(hi)); return r;
}
__device__ __forceinline__ void unpack2f(u64 v, float& lo, float& hi) {
    asm("mov.b64 {%0,%1}, %2;" : "=f"(lo), "=f"(hi) : "l"(v));
}
__device__ __forceinline__ u64 fma2f(u64 a, u64 b, u64 c) {
    u64 d; asm("fma.rn.f32x2 %0, %1, %2, %3;" : "=l"(d) : "l"(a), "l"(b), "l"(c)); return d;
}

// ---------------- prep: dtype-detect + per-batch counting sort + agg zero ----------------
__global__ void prep_kernel(const void* __restrict__ cl) {
    __shared__ int cnt[SS];
    __shared__ int cur[SS];
    __shared__ int isll;
    int b = blockIdx.x, tid = threadIdx.x;
    if (tid == 0) {
        const long long* p = (const long long*)cl;
        int ok = 1;
        for (int i = 0; i < 16; i++) { long long v = p[i]; if (v < 0 || v >= SS) ok = 0; }
        isll = ok;
    }
    if (tid < SS) cnt[tid] = 0;
    // zero this batch's agg slices while we're here
    float* a0 = d_agg0 + b * SS * HH;
    float* a1 = d_agg1 + b * SS * HH;
    float* a2 = d_agg2 + b * SS * HH;
    for (int i = tid; i < SS * HH; i += blockDim.x) { a0[i] = 0.f; a1[i] = 0.f; a2[i] = 0.f; }
    __syncthreads();
    const long long* p64 = (const long long*)cl;
    const int*       p32 = (const int*)cl;
    int l = isll;
    for (int n = tid; n < NN; n += blockDim.x) {
        int s = l ? (int)p64[(size_t)b * NN + n] : p32[(size_t)b * NN + n];
        atomicAdd(&cnt[s], 1);
    }
    __syncthreads();
    if (tid == 0) {
        int run = 0;
        for (int s = 0; s < SS; s++) { int c = cnt[s]; cur[s] = run; run += c; }
    }
    __syncthreads();
    for (int n = tid; n < NN; n += blockDim.x) {
        int s = l ? (int)p64[(size_t)b * NN + n] : p32[(size_t)b * NN + n];
        int r = atomicAdd(&cur[s], 1);
        d_perm[b * NN + r] = n;
        d_cs[b * NN + r]   = s;
    }
}

// ---------------- shared epilogue: LN -> relu -> (store h) -> match/REDUX segmented max ----------------
template <bool WRITE>
__device__ __forceinline__ void epilogue(float acc[HH], const float* gsm, const float* besm,
                                         int s, float* houtp, float* agg, int aggbase) {
    float sum = 0.f;
#pragma unroll
    for (int i = 0; i < HH; i++) sum += acc[i];
    float mu = sum * (1.0f / 64.0f);
    float ss = 0.f;
#pragma unroll
    for (int i = 0; i < HH; i++) { float d = acc[i] - mu; ss = fmaf(d, d, ss); }
    float rs = rsqrtf(ss * (1.0f / 64.0f) + 1e-5f);
#pragma unroll
    for (int i = 0; i < HH; i++) {
        float r = fmaxf(fmaf((acc[i] - mu) * rs, gsm[i], besm[i]), 0.0f);
        if (WRITE) houtp[(size_t)i * NN] = r;
        acc[i] = r;
    }
    // segmented warp max: lanes with equal cluster id form a group (sorted -> contiguous)
    unsigned match = __match_any_sync(0xffffffffu, s);
    bool leader = ((threadIdx.x & 31) == (__ffs(match) - 1));
#pragma unroll
    for (int i = 0; i < HH; i++) {
        // post-ReLU values are >= 0: float bit pattern is monotone as signed int
        int m = __reduce_max_sync(match, __float_as_int(acc[i]));
        if (leader) atomicMax((int*)(agg + aggbase + i), m);
    }
}

// ---------------- layer 0: gather x via perm, 8->64 matvec, LN/relu, write h0 + agg0 ----------------
__global__ __launch_bounds__(256) void layer0_kernel(const float* __restrict__ x,
                                                     const float* __restrict__ W0,
                                                     const float* __restrict__ b0,
                                                     const float* __restrict__ g0,
                                                     const float* __restrict__ be0) {
    __shared__ __align__(16) float Wsm[8 * HH];
    __shared__ __align__(16) float bsm[HH];
    __shared__ float gsm[HH], besm[HH];
    int tid = threadIdx.x, b = blockIdx.y;
    int rank = blockIdx.x * 256 + tid;
    for (int i = tid; i < 8 * HH; i += 256) Wsm[i] = W0[i];
    if (tid < HH) { bsm[tid] = b0[tid]; gsm[tid] = g0[tid]; besm[tid] = be0[tid]; }
    __syncthreads();
    int n = d_perm[b * NN + rank];
    int s = d_cs[b * NN + rank];
    const float4* xp = (const float4*)(x + ((size_t)b * NN + n) * 8);
    float4 xa = xp[0], xb = xp[1];
    float xv[8] = {xa.x, xa.y, xa.z, xa.w, xb.x, xb.y, xb.z, xb.w};
    u64 acc2[32];
    const u64* bp = (const u64*)bsm;
#pragma unroll
    for (int i = 0; i < 32; i++) acc2[i] = bp[i];
#pragma unroll
    for (int k = 0; k < 8; k++) {
        u64 h2 = pack2f(xv[k], xv[k]);
        const ulonglong2* wr = (const ulonglong2*)(Wsm + k * HH);
#pragma unroll
        for (int i = 0; i < 16; i++) {
            ulonglong2 w = wr[i];
            acc2[2 * i]     = fma2f(h2, w.x, acc2[2 * i]);
            acc2[2 * i + 1] = fma2f(h2, w.y, acc2[2 * i + 1]);
        }
    }
    float acc[HH];
#pragma unroll
    for (int i = 0; i < 32; i++) unpack2f(acc2[i], acc[2 * i], acc[2 * i + 1]);
    epilogue<true>(acc, gsm, besm, s, d_h0 + ((size_t)b * HH) * NN + rank,
                   d_agg0, ((b << 6) + s) << 6);
}

// ---------------- tiny GEMM: aggW[b] = bias + agg[b] @ W_bot (thread-per-output) ----------------
__global__ __launch_bounds__(256) void smallmm_kernel(const float* __restrict__ Wfull,
                                                      const float* __restrict__ bias, int stage) {
    __shared__ float Wsm[HH * HH];
    __shared__ float bsm[HH];
    const float* Wbot = Wfull + 64 * HH;   // rows 64..127 of the 128x64 weight
    const float* agg = (stage == 0) ? d_agg0 : d_agg1;
    int tid = threadIdx.x;
    int gid = blockIdx.x * 256 + tid;      // 524288 outputs over 2048 blocks
    for (int i = tid; i < HH * HH; i += 256) Wsm[i] = Wbot[i];
    if (tid < HH) bsm[tid] = bias[tid];
    __syncthreads();
    int c = gid & 63;
    int row = gid >> 6;                    // (b*64 + srow)
    const float* A = agg + (row << 6);
    float a = bsm[c];
#pragma unroll 8
    for (int k = 0; k < HH; k++) a = fmaf(A[k], Wsm[(k << 6) + c], a);
    d_aggW[gid] = a;
}

// ---------------- layers 1/2: 64->64 matvec (h@W_top + aggW[s]), LN/relu, agg ----------------
template <int STAGE>
__global__ __launch_bounds__(256) void layer12_kernel(const float* __restrict__ W,
                                                      const float* __restrict__ g,
                                                      const float* __restrict__ be) {
    __shared__ __align__(16) float Wsm[HH * HH];
    __shared__ float gsm[HH], besm[HH];
    int tid = threadIdx.x, b = blockIdx.y;
    int rank = blockIdx.x * 256 + tid;
    for (int i = tid; i < (HH * HH) / 4; i += 256) ((float4*)Wsm)[i] = ((const float4*)W)[i];
    if (tid < HH) { gsm[tid] = g[tid]; besm[tid] = be[tid]; }
    __syncthreads();
    int s = d_cs[b * NN + rank];
    const u64* aw = (const u64*)(d_aggW + (((size_t)b * SS + s) << 6));
    u64 acc2[32];
#pragma unroll
    for (int i = 0; i < 32; i++) acc2[i] = aw[i];   // bias already folded in
    const float* hp = ((STAGE == 1) ? d_h0 : d_h1) + ((size_t)b * HH) * NN + rank;
    for (int k0 = 0; k0 < HH; k0 += 8) {
        float hk[8];
#pragma unroll
        for (int j = 0; j < 8; j++) hk[j] = hp[(size_t)(k0 + j) * NN];
#pragma unroll
        for (int j = 0; j < 8; j++) {
            u64 h2 = pack2f(hk[j], hk[j]);
            const ulonglong2* wr = (const ulonglong2*)(Wsm + (k0 + j) * HH);
#pragma unroll
            for (int i = 0; i < 16; i++) {
                ulonglong2 w = wr[i];
                acc2[2 * i]     = fma2f(h2, w.x, acc2[2 * i]);
                acc2[2 * i + 1] = fma2f(h2, w.y, acc2[2 * i + 1]);
            }
        }
    }
    float acc[HH];
#pragma unroll
    for (int i = 0; i < 32; i++) unpack2f(acc2[i], acc[2 * i], acc[2 * i + 1]);
    float* houtp = (STAGE == 1) ? (d_h1 + ((size_t)b * HH) * NN + rank) : (float*)0;
    epilogue<(STAGE == 1)>(acc, gsm, besm, s, houtp,
                           (STAGE == 1) ? d_agg1 : d_agg2, ((b << 6) + s) << 6);
}

// ---------------- final: out[b,s,c]=out[b,s,64+c]=agg2[b,s,c]/max(||col||, eps) ----------------
__global__ void final_kernel(float* __restrict__ out) {
    int b = blockIdx.x;
    int c = threadIdx.x;   // 64 threads, one per channel
    const float* a = d_agg2 + b * SS * HH;
    float ss = 0.f;
#pragma unroll 8
    for (int s = 0; s < SS; s++) { float v = a[s * HH + c]; ss = fmaf(v, v, ss); }
    float inv = 1.0f / fmaxf(sqrtf(ss), 1e-12f);
    for (int s = 0; s < SS; s++) {
        float o = a[s * HH + c] * inv;
        out[((size_t)(b * SS + s)) * 128 + c]      = o;
        out[((size_t)(b * SS + s)) * 128 + 64 + c] = o;
    }
}

// ---------------- launch ----------------
extern "C" void kernel_launch(void* const* d_in, const int* in_sizes, int n_in,
                              void* d_out, int out_size) {
    const float* x  = (const float*)d_in[0];
    const void*  cl = d_in[1];
    const float* W0 = (const float*)d_in[2];
    const float* b0 = (const float*)d_in[3];
    const float* g0 = (const float*)d_in[4];
    const float* e0 = (const float*)d_in[5];
    const float* W1 = (const float*)d_in[6];
    const float* b1 = (const float*)d_in[7];
    const float* g1 = (const float*)d_in[8];
    const float* e1 = (const float*)d_in[9];
    const float* W2 = (const float*)d_in[10];
    const float* b2 = (const float*)d_in[11];
    const float* g2 = (const float*)d_in[12];
    const float* e2 = (const float*)d_in[13];
    float* out = (float*)d_out;

    const int SMALLMM_BLOCKS = (BB * SS * HH) / 256;               // 2048 (bugfix: was /64 too small)

    prep_kernel<<<BB, 256>>>(cl);                                  // launch 1
    layer0_kernel<<<dim3(NN / 256, BB), 256>>>(x, W0, b0, g0, e0); // launch 2
    smallmm_kernel<<<SMALLMM_BLOCKS, 256>>>(W1, b1, 0);            // launch 3
    layer12_kernel<1><<<dim3(NN / 256, BB), 256>>>(W1, g1, e1);    // launch 4
    smallmm_kernel<<<SMALLMM_BLOCKS, 256>>>(W2, b2, 1);            // launch 5
    layer12_kernel<2><<<dim3(NN / 256, BB), 256>>>(W2, g2, e2);    // launch 6  <- ncu -s5 -c1
    final_kernel<<<BB, 64>>>(out);                                 // launch 7
}

// round 6
// speedup vs baseline: 1.4364x; 1.4364x over previous
#include <cuda_runtime.h>
#include <cstdint>
#include <cstddef>

#define BB 128
#define NN 2048
#define HH 64
#define SS 64

typedef unsigned long long u64;

// ---------------- scratch (static device memory; no allocation) ----------------
__device__ __align__(256) float d_h0[(size_t)BB * HH * NN];   // 64 MB, [b][c][rank]
__device__ __align__(256) float d_h1[(size_t)BB * HH * NN];   // 64 MB
__device__ __align__(256) float d_agg0[BB * SS * HH];
__device__ __align__(256) float d_agg1[BB * SS * HH];
__device__ __align__(256) float d_agg2[BB * SS * HH];
__device__ __align__(256) float d_aggW[BB * SS * HH];         // bias + agg@W_bot, per layer
__device__ int            d_perm[BB * NN];
__device__ int            d_cs[BB * NN];                      // sorted cluster ids

// ---------------- f32x2 packed fp32 helpers (bit-exact IEEE fma on both halves) ----------------
__device__ __forceinline__ u64 pack2f(float lo, float hi) {
    u64 r; asm("mov.b64 %0, {%1,%2};" : "=l"(r) : "f"(lo), "f"(hi)); return r;
}
__device__ __forceinline__ void unpack2f(u64 v, float& lo, float& hi) {
    asm("mov.b64 {%0,%1}, %2;" : "=f"(lo), "=f"(hi) : "l"(v));
}
__device__ __forceinline__ u64 fma2f(u64 a, u64 b, u64 c) {
    u64 d; asm("fma.rn.f32x2 %0, %1, %2, %3;" : "=l"(d) : "l"(a), "l"(b), "l"(c)); return d;
}

// ---------------- prep: dtype-detect + per-batch counting sort + agg zero ----------------
__global__ void prep_kernel(const void* __restrict__ cl) {
    __shared__ int cnt[SS];
    __shared__ int cur[SS];
    __shared__ int isll;
    int b = blockIdx.x, tid = threadIdx.x;
    if (tid == 0) {
        const long long* p = (const long long*)cl;
        int ok = 1;
        for (int i = 0; i < 16; i++) { long long v = p[i]; if (v < 0 || v >= SS) ok = 0; }
        isll = ok;
    }
    if (tid < SS) cnt[tid] = 0;
    float* a0 = d_agg0 + b * SS * HH;
    float* a1 = d_agg1 + b * SS * HH;
    float* a2 = d_agg2 + b * SS * HH;
    for (int i = tid; i < SS * HH; i += blockDim.x) { a0[i] = 0.f; a1[i] = 0.f; a2[i] = 0.f; }
    __syncthreads();
    const long long* p64 = (const long long*)cl;
    const int*       p32 = (const int*)cl;
    int l = isll;
    for (int n = tid; n < NN; n += blockDim.x) {
        int s = l ? (int)p64[(size_t)b * NN + n] : p32[(size_t)b * NN + n];
        atomicAdd(&cnt[s], 1);
    }
    __syncthreads();
    if (tid == 0) {
        int run = 0;
        for (int s = 0; s < SS; s++) { int c = cnt[s]; cur[s] = run; run += c; }
    }
    __syncthreads();
    for (int n = tid; n < NN; n += blockDim.x) {
        int s = l ? (int)p64[(size_t)b * NN + n] : p32[(size_t)b * NN + n];
        int r = atomicAdd(&cur[s], 1);
        d_perm[b * NN + r] = n;
        d_cs[b * NN + r]   = s;
    }
}

// ---------------- layer 0: gather x via perm, 8->64 matvec, LN/relu, write h0 + agg0 ----------------
__global__ __launch_bounds__(256) void layer0_kernel(const float* __restrict__ x,
                                                     const float* __restrict__ W0,
                                                     const float* __restrict__ b0,
                                                     const float* __restrict__ g0,
                                                     const float* __restrict__ be0) {
    __shared__ __align__(16) float Wsm[8 * HH];
    __shared__ float bsm[HH], gsm[HH], besm[HH];
    int tid = threadIdx.x, b = blockIdx.y;
    int rank = blockIdx.x * 256 + tid;
    for (int i = tid; i < 8 * HH; i += 256) Wsm[i] = W0[i];
    if (tid < HH) { bsm[tid] = b0[tid]; gsm[tid] = g0[tid]; besm[tid] = be0[tid]; }
    __syncthreads();
    int n = d_perm[b * NN + rank];
    int s = d_cs[b * NN + rank];
    const float4* xp = (const float4*)(x + ((size_t)b * NN + n) * 8);
    float4 xa = xp[0], xb = xp[1];
    float xv[8] = {xa.x, xa.y, xa.z, xa.w, xb.x, xb.y, xb.z, xb.w};
    float acc[HH];
#pragma unroll
    for (int i = 0; i < HH; i++) acc[i] = bsm[i];
#pragma unroll
    for (int k = 0; k < 8; k++) {
        float h = xv[k];
        const float* wr = Wsm + k * HH;
#pragma unroll
        for (int i = 0; i < HH; i++) acc[i] = fmaf(h, wr[i], acc[i]);
    }
    // LN + relu
    float sum = 0.f;
#pragma unroll
    for (int i = 0; i < HH; i++) sum += acc[i];
    float mu = sum * (1.0f / 64.0f);
    float ssq = 0.f;
#pragma unroll
    for (int i = 0; i < HH; i++) { float d = acc[i] - mu; ssq = fmaf(d, d, ssq); }
    float rs = rsqrtf(ssq * (1.0f / 64.0f) + 1e-5f);
    float* houtp = d_h0 + ((size_t)b * HH) * NN + rank;
#pragma unroll
    for (int i = 0; i < HH; i++) {
        float r = fmaxf(fmaf((acc[i] - mu) * rs, gsm[i], besm[i]), 0.0f);
        houtp[(size_t)i * NN] = r;
        acc[i] = r;
    }
    // segmented warp max via match/redux (sorted -> contiguous groups)
    unsigned match = __match_any_sync(0xffffffffu, s);
    bool leader = ((threadIdx.x & 31) == (__ffs(match) - 1));
    float* agg = d_agg0 + (((b << 6) + s) << 6);
#pragma unroll
    for (int i = 0; i < HH; i++) {
        int m = __reduce_max_sync(match, __float_as_int(acc[i]));
        if (leader) atomicMax((int*)(agg + i), m);
    }
}

// ---------------- tiny GEMM: aggW[b] = bias + agg[b] @ W_bot (thread-per-output) ----------------
__global__ __launch_bounds__(256) void smallmm_kernel(const float* __restrict__ Wfull,
                                                      const float* __restrict__ bias, int stage) {
    __shared__ float Wsm[HH * HH];
    __shared__ float bsm[HH];
    const float* Wbot = Wfull + 64 * HH;
    const float* agg = (stage == 0) ? d_agg0 : d_agg1;
    int tid = threadIdx.x;
    int gid = blockIdx.x * 256 + tid;
    for (int i = tid; i < HH * HH; i += 256) Wsm[i] = Wbot[i];
    if (tid < HH) bsm[tid] = bias[tid];
    __syncthreads();
    int c = gid & 63;
    int row = gid >> 6;
    const float* A = agg + (row << 6);
    float a = bsm[c];
#pragma unroll 8
    for (int k = 0; k < HH; k++) a = fmaf(A[k], Wsm[(k << 6) + c], a);
    d_aggW[gid] = a;
}

// ---------------- layers 1/2: register-blocked GEMM, P=4 points x C=8 channels per thread ----
// block 256 threads = 32 point-groups x 8 channel-groups; tile = 128 points x 64 channels.
template <int STAGE>
__global__ __launch_bounds__(256, 3) void layer12_kernel(const float* __restrict__ W,
                                                         const float* __restrict__ g,
                                                         const float* __restrict__ be) {
    __shared__ __align__(16) float wsm[HH * HH];     // 16 KB, [k][c]
    __shared__ __align__(16) float hsm[16 * 128];    // 8 KB chunk, [r][point]
    __shared__ float gsm[HH], besm[HH];
    int tid = threadIdx.x, b = blockIdx.y;
    int pg = tid >> 3;          // 0..31
    int cg = tid & 7;           // 0..7
    int pbase = blockIdx.x * 128;
    int p0 = pbase + pg * 4;    // first of this thread's 4 points

    for (int i = tid; i < (HH * HH) / 4; i += 256) ((float4*)wsm)[i] = ((const float4*)W)[i];
    if (tid < HH) { gsm[tid] = g[tid]; besm[tid] = be[tid]; }

    // per-point cluster ids + acc init from aggW[s] (bias folded in)
    int sj[4];
    u64 acc2[4][4];
#pragma unroll
    for (int j = 0; j < 4; j++) {
        sj[j] = d_cs[b * NN + p0 + j];
        const float4* aw = (const float4*)(d_aggW + (((size_t)b * SS + sj[j]) << 6) + cg * 8);
        float4 a0 = aw[0], a1 = aw[1];
        acc2[j][0] = pack2f(a0.x, a0.y);
        acc2[j][1] = pack2f(a0.z, a0.w);
        acc2[j][2] = pack2f(a1.x, a1.y);
        acc2[j][3] = pack2f(a1.z, a1.w);
    }

    const float* hbase = ((STAGE == 1) ? d_h0 : d_h1) + ((size_t)b * HH) * NN + pbase;

    for (int kc = 0; kc < 4; kc++) {
        __syncthreads();
        // stage 16 k-rows x 128 points (coalesced: rows are contiguous in [c][rank] layout)
        for (int i = tid; i < 512; i += 256) {
            int r = i >> 5, c4 = i & 31;
            ((float4*)hsm)[r * 32 + c4] =
                *(const float4*)(hbase + (size_t)(kc * 16 + r) * NN + c4 * 4);
        }
        __syncthreads();
#pragma unroll
        for (int r = 0; r < 16; r++) {
            int k = kc * 16 + r;
            float4 h4 = *(const float4*)(hsm + r * 128 + pg * 4);
            u64 hs0 = pack2f(h4.x, h4.x);
            u64 hs1 = pack2f(h4.y, h4.y);
            u64 hs2 = pack2f(h4.z, h4.z);
            u64 hs3 = pack2f(h4.w, h4.w);
            const float4* wrow = (const float4*)(wsm + k * HH + cg * 8);
            float4 w0 = wrow[0], w1 = wrow[1];
            u64 wp0 = pack2f(w0.x, w0.y);
            u64 wp1 = pack2f(w0.z, w0.w);
            u64 wp2 = pack2f(w1.x, w1.y);
            u64 wp3 = pack2f(w1.z, w1.w);
            acc2[0][0] = fma2f(hs0, wp0, acc2[0][0]);
            acc2[0][1] = fma2f(hs0, wp1, acc2[0][1]);
            acc2[0][2] = fma2f(hs0, wp2, acc2[0][2]);
            acc2[0][3] = fma2f(hs0, wp3, acc2[0][3]);
            acc2[1][0] = fma2f(hs1, wp0, acc2[1][0]);
            acc2[1][1] = fma2f(hs1, wp1, acc2[1][1]);
            acc2[1][2] = fma2f(hs1, wp2, acc2[1][2]);
            acc2[1][3] = fma2f(hs1, wp3, acc2[1][3]);
            acc2[2][0] = fma2f(hs2, wp0, acc2[2][0]);
            acc2[2][1] = fma2f(hs2, wp1, acc2[2][1]);
            acc2[2][2] = fma2f(hs2, wp2, acc2[2][2]);
            acc2[2][3] = fma2f(hs2, wp3, acc2[2][3]);
            acc2[3][0] = fma2f(hs3, wp0, acc2[3][0]);
            acc2[3][1] = fma2f(hs3, wp1, acc2[3][1]);
            acc2[3][2] = fma2f(hs3, wp2, acc2[3][2]);
            acc2[3][3] = fma2f(hs3, wp3, acc2[3][3]);
        }
    }

    float acc[4][8];
#pragma unroll
    for (int j = 0; j < 4; j++)
#pragma unroll
        for (int i = 0; i < 4; i++) unpack2f(acc2[j][i], acc[j][2 * i], acc[j][2 * i + 1]);

    // LN mean: partial sums, butterfly over the 8 channel-group lanes (lane bits 0..2)
    const unsigned fm = 0xffffffffu;
    float s1[4];
#pragma unroll
    for (int j = 0; j < 4; j++) {
        float t = 0.f;
#pragma unroll
        for (int i = 0; i < 8; i++) t += acc[j][i];
        s1[j] = t;
    }
#pragma unroll
    for (int d = 1; d < 8; d <<= 1)
#pragma unroll
        for (int j = 0; j < 4; j++) s1[j] += __shfl_xor_sync(fm, s1[j], d);
    float mu[4];
#pragma unroll
    for (int j = 0; j < 4; j++) mu[j] = s1[j] * (1.0f / 64.0f);
    // LN var: two-pass
    float s2[4];
#pragma unroll
    for (int j = 0; j < 4; j++) {
        float t = 0.f;
#pragma unroll
        for (int i = 0; i < 8; i++) { float d = acc[j][i] - mu[j]; t = fmaf(d, d, t); }
        s2[j] = t;
    }
#pragma unroll
    for (int d = 1; d < 8; d <<= 1)
#pragma unroll
        for (int j = 0; j < 4; j++) s2[j] += __shfl_xor_sync(fm, s2[j], d);
    float rs[4];
#pragma unroll
    for (int j = 0; j < 4; j++) rs[j] = rsqrtf(s2[j] * (1.0f / 64.0f) + 1e-5f);

    // normalize + relu
#pragma unroll
    for (int j = 0; j < 4; j++)
#pragma unroll
        for (int i = 0; i < 8; i++) {
            int c = cg * 8 + i;
            acc[j][i] = fmaxf(fmaf((acc[j][i] - mu[j]) * rs[j], gsm[c], besm[c]), 0.0f);
        }

    // write h (STAGE 1 only): one float4 per channel covering the 4 consecutive points
    if (STAGE == 1) {
        float* hout = d_h1 + ((size_t)b * HH) * NN + p0;
#pragma unroll
        for (int i = 0; i < 8; i++) {
            int c = cg * 8 + i;
            float4 v = make_float4(acc[0][i], acc[1][i], acc[2][i], acc[3][i]);
            *(float4*)(hout + (size_t)c * NN) = v;
        }
    }

    // segmented max over this thread's 4 consecutive (sorted) points: run-flush with atomics
    float* agg = ((STAGE == 1) ? d_agg1 : d_agg2) + ((size_t)b << 12);
    float run[8];
#pragma unroll
    for (int i = 0; i < 8; i++) run[i] = acc[0][i];
    int sprev = sj[0];
#pragma unroll
    for (int j = 1; j < 4; j++) {
        if (sj[j] == sprev) {
#pragma unroll
            for (int i = 0; i < 8; i++) run[i] = fmaxf(run[i], acc[j][i]);
        } else {
            float* dst = agg + (sprev << 6) + cg * 8;
#pragma unroll
            for (int i = 0; i < 8; i++) atomicMax((int*)(dst + i), __float_as_int(run[i]));
            sprev = sj[j];
#pragma unroll
            for (int i = 0; i < 8; i++) run[i] = acc[j][i];
        }
    }
    {
        float* dst = agg + (sprev << 6) + cg * 8;
#pragma unroll
        for (int i = 0; i < 8; i++) atomicMax((int*)(dst + i), __float_as_int(run[i]));
    }
}

// ---------------- final: out[b,s,c]=out[b,s,64+c]=agg2[b,s,c]/max(||col||, eps) ----------------
__global__ void final_kernel(float* __restrict__ out) {
    int b = blockIdx.x;
    int c = threadIdx.x;
    const float* a = d_agg2 + b * SS * HH;
    float ss = 0.f;
#pragma unroll 8
    for (int s = 0; s < SS; s++) { float v = a[s * HH + c]; ss = fmaf(v, v, ss); }
    float inv = 1.0f / fmaxf(sqrtf(ss), 1e-12f);
    for (int s = 0; s < SS; s++) {
        float o = a[s * HH + c] * inv;
        out[((size_t)(b * SS + s)) * 128 + c]      = o;
        out[((size_t)(b * SS + s)) * 128 + 64 + c] = o;
    }
}

// ---------------- launch ----------------
extern "C" void kernel_launch(void* const* d_in, const int* in_sizes, int n_in,
                              void* d_out, int out_size) {
    const float* x  = (const float*)d_in[0];
    const void*  cl = d_in[1];
    const float* W0 = (const float*)d_in[2];
    const float* b0 = (const float*)d_in[3];
    const float* g0 = (const float*)d_in[4];
    const float* e0 = (const float*)d_in[5];
    const float* W1 = (const float*)d_in[6];
    const float* b1 = (const float*)d_in[7];
    const float* g1 = (const float*)d_in[8];
    const float* e1 = (const float*)d_in[9];
    const float* W2 = (const float*)d_in[10];
    const float* b2 = (const float*)d_in[11];
    const float* g2 = (const float*)d_in[12];
    const float* e2 = (const float*)d_in[13];
    float* out = (float*)d_out;

    const int SMALLMM_BLOCKS = (BB * SS * HH) / 256;               // 2048

    prep_kernel<<<BB, 256>>>(cl);                                  // 1
    layer0_kernel<<<dim3(NN / 256, BB), 256>>>(x, W0, b0, g0, e0); // 2
    smallmm_kernel<<<SMALLMM_BLOCKS, 256>>>(W1, b1, 0);            // 3
    layer12_kernel<1><<<dim3(NN / 128, BB), 256>>>(W1, g1, e1);    // 4
    smallmm_kernel<<<SMALLMM_BLOCKS, 256>>>(W2, b2, 1);            // 5
    layer12_kernel<2><<<dim3(NN / 128, BB), 256>>>(W2, g2, e2);    // 6  <- ncu -s5 -c1
    final_kernel<<<BB, 64>>>(out);                                 // 7
}

// round 7
// speedup vs baseline: 1.7678x; 1.2307x over previous
#include <cuda_runtime.h>
#include <cstdint>
#include <cstddef>

#define BB 128
#define NN 2048
#define HH 64
#define SS 64

typedef unsigned long long u64;

// ---------------- scratch (static device memory; no allocation) ----------------
__device__ __align__(256) float d_h0[(size_t)BB * HH * NN];   // 64 MB, [b][c][rank]
__device__ __align__(256) float d_h1[(size_t)BB * HH * NN];   // 64 MB
__device__ __align__(256) float d_agg0[BB * SS * HH];
__device__ __align__(256) float d_agg1[BB * SS * HH];
__device__ __align__(256) float d_agg2[BB * SS * HH];
__device__ __align__(256) float d_aggW[BB * SS * HH];         // bias + agg@W_bot, per layer
__device__ int            d_perm[BB * NN];
__device__ int            d_cs[BB * NN];                      // sorted cluster ids

// ---------------- f32x2 packed fp32 helpers (bit-exact IEEE fma on both halves) ----------------
__device__ __forceinline__ u64 pack2f(float lo, float hi) {
    u64 r; asm("mov.b64 %0, {%1,%2};" : "=l"(r) : "f"(lo), "f"(hi)); return r;
}
__device__ __forceinline__ void unpack2f(u64 v, float& lo, float& hi) {
    asm("mov.b64 {%0,%1}, %2;" : "=f"(lo), "=f"(hi) : "l"(v));
}
__device__ __forceinline__ u64 fma2f(u64 a, u64 b, u64 c) {
    u64 d; asm("fma.rn.f32x2 %0, %1, %2, %3;" : "=l"(d) : "l"(a), "l"(b), "l"(c)); return d;
}

// ---------------- prep: dtype-detect + per-batch counting sort + agg zero ----------------
__global__ void prep_kernel(const void* __restrict__ cl) {
    __shared__ int cnt[SS];
    __shared__ int cur[SS];
    __shared__ int isll;
    int b = blockIdx.x, tid = threadIdx.x;
    if (tid == 0) {
        const long long* p = (const long long*)cl;
        int ok = 1;
        for (int i = 0; i < 16; i++) { long long v = p[i]; if (v < 0 || v >= SS) ok = 0; }
        isll = ok;
    }
    if (tid < SS) cnt[tid] = 0;
    float* a0 = d_agg0 + b * SS * HH;
    float* a1 = d_agg1 + b * SS * HH;
    float* a2 = d_agg2 + b * SS * HH;
    for (int i = tid; i < SS * HH; i += blockDim.x) { a0[i] = 0.f; a1[i] = 0.f; a2[i] = 0.f; }
    __syncthreads();
    const long long* p64 = (const long long*)cl;
    const int*       p32 = (const int*)cl;
    int l = isll;
    for (int n = tid; n < NN; n += blockDim.x) {
        int s = l ? (int)p64[(size_t)b * NN + n] : p32[(size_t)b * NN + n];
        atomicAdd(&cnt[s], 1);
    }
    __syncthreads();
    if (tid == 0) {
        int run = 0;
        for (int s = 0; s < SS; s++) { int c = cnt[s]; cur[s] = run; run += c; }
    }
    __syncthreads();
    for (int n = tid; n < NN; n += blockDim.x) {
        int s = l ? (int)p64[(size_t)b * NN + n] : p32[(size_t)b * NN + n];
        int r = atomicAdd(&cur[s], 1);
        d_perm[b * NN + r] = n;
        d_cs[b * NN + r]   = s;
    }
}

// ---------------- layer 0: gather x via perm, 8->64 matvec, LN/relu, write h0 + agg0 ----------------
__global__ __launch_bounds__(256) void layer0_kernel(const float* __restrict__ x,
                                                     const float* __restrict__ W0,
                                                     const float* __restrict__ b0,
                                                     const float* __restrict__ g0,
                                                     const float* __restrict__ be0) {
    __shared__ __align__(16) float Wsm[8 * HH];
    __shared__ float bsm[HH], gsm[HH], besm[HH];
    int tid = threadIdx.x, b = blockIdx.y;
    int rank = blockIdx.x * 256 + tid;
    for (int i = tid; i < 8 * HH; i += 256) Wsm[i] = W0[i];
    if (tid < HH) { bsm[tid] = b0[tid]; gsm[tid] = g0[tid]; besm[tid] = be0[tid]; }
    __syncthreads();
    int n = d_perm[b * NN + rank];
    int s = d_cs[b * NN + rank];
    const float4* xp = (const float4*)(x + ((size_t)b * NN + n) * 8);
    float4 xa = xp[0], xb = xp[1];
    float xv[8] = {xa.x, xa.y, xa.z, xa.w, xb.x, xb.y, xb.z, xb.w};
    float acc[HH];
#pragma unroll
    for (int i = 0; i < HH; i++) acc[i] = bsm[i];
#pragma unroll
    for (int k = 0; k < 8; k++) {
        float h = xv[k];
        const float* wr = Wsm + k * HH;
#pragma unroll
        for (int i = 0; i < HH; i++) acc[i] = fmaf(h, wr[i], acc[i]);
    }
    float sum = 0.f;
#pragma unroll
    for (int i = 0; i < HH; i++) sum += acc[i];
    float mu = sum * (1.0f / 64.0f);
    float ssq = 0.f;
#pragma unroll
    for (int i = 0; i < HH; i++) { float d = acc[i] - mu; ssq = fmaf(d, d, ssq); }
    float rs = rsqrtf(ssq * (1.0f / 64.0f) + 1e-5f);
    float* houtp = d_h0 + ((size_t)b * HH) * NN + rank;
#pragma unroll
    for (int i = 0; i < HH; i++) {
        float r = fmaxf(fmaf((acc[i] - mu) * rs, gsm[i], besm[i]), 0.0f);
        houtp[(size_t)i * NN] = r;
        acc[i] = r;
    }
    unsigned match = __match_any_sync(0xffffffffu, s);
    bool leader = ((threadIdx.x & 31) == (__ffs(match) - 1));
    float* agg = d_agg0 + (((b << 6) + s) << 6);
#pragma unroll
    for (int i = 0; i < HH; i++) {
        int m = __reduce_max_sync(match, __float_as_int(acc[i]));
        if (leader) atomicMax((int*)(agg + i), m);
    }
}

// ---------------- tiny GEMM: aggW[b] = bias + agg[b] @ W_bot (thread-per-output) ----------------
__global__ __launch_bounds__(256) void smallmm_kernel(const float* __restrict__ Wfull,
                                                      const float* __restrict__ bias, int stage) {
    __shared__ float Wsm[HH * HH];
    __shared__ float bsm[HH];
    const float* Wbot = Wfull + 64 * HH;
    const float* agg = (stage == 0) ? d_agg0 : d_agg1;
    int tid = threadIdx.x;
    int gid = blockIdx.x * 256 + tid;
    for (int i = tid; i < HH * HH; i += 256) Wsm[i] = Wbot[i];
    if (tid < HH) bsm[tid] = bias[tid];
    __syncthreads();
    int c = gid & 63;
    int row = gid >> 6;
    const float* A = agg + (row << 6);
    float a = bsm[c];
#pragma unroll 8
    for (int k = 0; k < HH; k++) a = fmaf(A[k], Wsm[(k << 6) + c], a);
    d_aggW[gid] = a;
}

// ---------------- layers 1/2: register-blocked GEMM, P=8 points x C=8 channels per thread ----
// block 256 threads = 32 point-groups x 8 channel-groups; tile = 256 points x 64 channels.
// W stored swizzled: float4 j of row k at slot ((j&1)<<3)|(j>>1)  -> both per-thread W
// LDS.128 reads are contiguous 128B across the 8 cg lanes (conflict-free).
template <int STAGE>
__global__ __launch_bounds__(256, 2) void layer12_kernel(const float* __restrict__ W,
                                                         const float* __restrict__ g,
                                                         const float* __restrict__ be) {
    __shared__ __align__(16) float wsm[HH * HH];     // 16 KB, swizzled [k][slot]
    __shared__ __align__(16) float hsm[16 * 256];    // 16 KB chunk, [r][point]
    __shared__ float gsm[HH], besm[HH];
    int tid = threadIdx.x, b = blockIdx.y;
    int pg = tid >> 3;          // 0..31
    int cg = tid & 7;           // 0..7
    int pbase = blockIdx.x * 256;
    int p0 = pbase + pg * 8;    // first of this thread's 8 points

    // stage W with swizzle
    for (int i = tid; i < (HH * HH) / 4; i += 256) {
        int k = i >> 4, j = i & 15;
        int slot = ((j & 1) << 3) | (j >> 1);
        ((float4*)wsm)[k * 16 + slot] = ((const float4*)W)[i];
    }
    if (tid < HH) { gsm[tid] = g[tid]; besm[tid] = be[tid]; }

    // per-point cluster ids (8 consecutive ints = 2 int4)
    int sj[8];
    {
        const int4* cp = (const int4*)(d_cs + b * NN + p0);
        int4 c0 = cp[0], c1 = cp[1];
        sj[0] = c0.x; sj[1] = c0.y; sj[2] = c0.z; sj[3] = c0.w;
        sj[4] = c1.x; sj[5] = c1.y; sj[6] = c1.z; sj[7] = c1.w;
    }
    // acc init from aggW[s] (bias folded in)
    u64 acc2[8][4];
#pragma unroll
    for (int j = 0; j < 8; j++) {
        const float4* aw = (const float4*)(d_aggW + (((size_t)b * SS + sj[j]) << 6) + cg * 8);
        float4 a0 = aw[0], a1 = aw[1];
        acc2[j][0] = pack2f(a0.x, a0.y);
        acc2[j][1] = pack2f(a0.z, a0.w);
        acc2[j][2] = pack2f(a1.x, a1.y);
        acc2[j][3] = pack2f(a1.z, a1.w);
    }

    const float* hbase = ((STAGE == 1) ? d_h0 : d_h1) + ((size_t)b * HH) * NN + pbase;

    for (int kc = 0; kc < 4; kc++) {
        __syncthreads();
        // stage 16 k-rows x 256 points (coalesced float4)
        for (int i = tid; i < 1024; i += 256) {
            int r = i >> 6, c4 = i & 63;
            ((float4*)hsm)[r * 64 + c4] =
                *(const float4*)(hbase + (size_t)(kc * 16 + r) * NN + c4 * 4);
        }
        __syncthreads();
#pragma unroll
        for (int r = 0; r < 16; r++) {
            int k = kc * 16 + r;
            const float4* hp4 = (const float4*)(hsm + r * 256 + pg * 8);
            float4 hA = hp4[0], hB = hp4[1];
            const float4* wrow = (const float4*)(wsm + k * HH);
            float4 w0 = wrow[cg], w1 = wrow[8 + cg];
            u64 wp0 = pack2f(w0.x, w0.y);
            u64 wp1 = pack2f(w0.z, w0.w);
            u64 wp2 = pack2f(w1.x, w1.y);
            u64 wp3 = pack2f(w1.z, w1.w);
            float hv[8] = {hA.x, hA.y, hA.z, hA.w, hB.x, hB.y, hB.z, hB.w};
#pragma unroll
            for (int j = 0; j < 8; j++) {
                u64 hs = pack2f(hv[j], hv[j]);
                acc2[j][0] = fma2f(hs, wp0, acc2[j][0]);
                acc2[j][1] = fma2f(hs, wp1, acc2[j][1]);
                acc2[j][2] = fma2f(hs, wp2, acc2[j][2]);
                acc2[j][3] = fma2f(hs, wp3, acc2[j][3]);
            }
        }
    }

    float acc[8][8];
#pragma unroll
    for (int j = 0; j < 8; j++)
#pragma unroll
        for (int i = 0; i < 4; i++) unpack2f(acc2[j][i], acc[j][2 * i], acc[j][2 * i + 1]);

    // LN mean/var: butterfly over the 8 channel-group lanes (lane bits 0..2)
    const unsigned fm = 0xffffffffu;
    float s1[8];
#pragma unroll
    for (int j = 0; j < 8; j++) {
        float t = 0.f;
#pragma unroll
        for (int i = 0; i < 8; i++) t += acc[j][i];
        s1[j] = t;
    }
#pragma unroll
    for (int d = 1; d < 8; d <<= 1)
#pragma unroll
        for (int j = 0; j < 8; j++) s1[j] += __shfl_xor_sync(fm, s1[j], d);
    float mu[8];
#pragma unroll
    for (int j = 0; j < 8; j++) mu[j] = s1[j] * (1.0f / 64.0f);
    float s2[8];
#pragma unroll
    for (int j = 0; j < 8; j++) {
        float t = 0.f;
#pragma unroll
        for (int i = 0; i < 8; i++) { float d = acc[j][i] - mu[j]; t = fmaf(d, d, t); }
        s2[j] = t;
    }
#pragma unroll
    for (int d = 1; d < 8; d <<= 1)
#pragma unroll
        for (int j = 0; j < 8; j++) s2[j] += __shfl_xor_sync(fm, s2[j], d);
    float rs[8];
#pragma unroll
    for (int j = 0; j < 8; j++) rs[j] = rsqrtf(s2[j] * (1.0f / 64.0f) + 1e-5f);

    // normalize + relu
#pragma unroll
    for (int j = 0; j < 8; j++)
#pragma unroll
        for (int i = 0; i < 8; i++) {
            int c = cg * 8 + i;
            acc[j][i] = fmaxf(fmaf((acc[j][i] - mu[j]) * rs[j], gsm[c], besm[c]), 0.0f);
        }

    // write h (STAGE 1 only): two float4 per channel covering the 8 consecutive points
    if (STAGE == 1) {
        float* hout = d_h1 + ((size_t)b * HH) * NN + p0;
#pragma unroll
        for (int i = 0; i < 8; i++) {
            int c = cg * 8 + i;
            float4 v0 = make_float4(acc[0][i], acc[1][i], acc[2][i], acc[3][i]);
            float4 v1 = make_float4(acc[4][i], acc[5][i], acc[6][i], acc[7][i]);
            *(float4*)(hout + (size_t)c * NN)     = v0;
            *(float4*)(hout + (size_t)c * NN + 4) = v1;
        }
    }

    // segmented max over this thread's 8 consecutive (sorted) points: run-flush with atomics
    float* agg = ((STAGE == 1) ? d_agg1 : d_agg2) + ((size_t)b << 12);
    float run[8];
#pragma unroll
    for (int i = 0; i < 8; i++) run[i] = acc[0][i];
    int sprev = sj[0];
#pragma unroll
    for (int j = 1; j < 8; j++) {
        if (sj[j] == sprev) {
#pragma unroll
            for (int i = 0; i < 8; i++) run[i] = fmaxf(run[i], acc[j][i]);
        } else {
            float* dst = agg + (sprev << 6) + cg * 8;
#pragma unroll
            for (int i = 0; i < 8; i++) atomicMax((int*)(dst + i), __float_as_int(run[i]));
            sprev = sj[j];
#pragma unroll
            for (int i = 0; i < 8; i++) run[i] = acc[j][i];
        }
    }
    {
        float* dst = agg + (sprev << 6) + cg * 8;
#pragma unroll
        for (int i = 0; i < 8; i++) atomicMax((int*)(dst + i), __float_as_int(run[i]));
    }
}

// ---------------- final: out[b,s,c]=out[b,s,64+c]=agg2[b,s,c]/max(||col||, eps) ----------------
__global__ void final_kernel(float* __restrict__ out) {
    int b = blockIdx.x;
    int c = threadIdx.x;
    const float* a = d_agg2 + b * SS * HH;
    float ss = 0.f;
#pragma unroll 8
    for (int s = 0; s < SS; s++) { float v = a[s * HH + c]; ss = fmaf(v, v, ss); }
    float inv = 1.0f / fmaxf(sqrtf(ss), 1e-12f);
    for (int s = 0; s < SS; s++) {
        float o = a[s * HH + c] * inv;
        out[((size_t)(b * SS + s)) * 128 + c]      = o;
        out[((size_t)(b * SS + s)) * 128 + 64 + c] = o;
    }
}

// ---------------- launch ----------------
extern "C" void kernel_launch(void* const* d_in, const int* in_sizes, int n_in,
                              void* d_out, int out_size) {
    const float* x  = (const float*)d_in[0];
    const void*  cl = d_in[1];
    const float* W0 = (const float*)d_in[2];
    const float* b0 = (const float*)d_in[3];
    const float* g0 = (const float*)d_in[4];
    const float* e0 = (const float*)d_in[5];
    const float* W1 = (const float*)d_in[6];
    const float* b1 = (const float*)d_in[7];
    const float* g1 = (const float*)d_in[8];
    const float* e1 = (const float*)d_in[9];
    const float* W2 = (const float*)d_in[10];
    const float* b2 = (const float*)d_in[11];
    const float* g2 = (const float*)d_in[12];
    const float* e2 = (const float*)d_in[13];
    float* out = (float*)d_out;

    const int SMALLMM_BLOCKS = (BB * SS * HH) / 256;               // 2048

    prep_kernel<<<BB, 256>>>(cl);                                  // 1
    layer0_kernel<<<dim3(NN / 256, BB), 256>>>(x, W0, b0, g0, e0); // 2
    smallmm_kernel<<<SMALLMM_BLOCKS, 256>>>(W1, b1, 0);            // 3
    layer12_kernel<1><<<dim3(NN / 256, BB), 256>>>(W1, g1, e1);    // 4
    smallmm_kernel<<<SMALLMM_BLOCKS, 256>>>(W2, b2, 1);            // 5
    layer12_kernel<2><<<dim3(NN / 256, BB), 256>>>(W2, g2, e2);    // 6  <- ncu -s5 -c1
    final_kernel<<<BB, 64>>>(out);                                 // 7
}

// round 8
// speedup vs baseline: 2.0931x; 1.1840x over previous
#include <cuda_runtime.h>
#include <cstdint>
#include <cstddef>

#define BB 128
#define NN 2048
#define HH 64
#define SS 64

typedef unsigned long long u64;

// ---------------- scratch (static device memory; no allocation) ----------------
__device__ __align__(256) float d_h0[(size_t)BB * HH * NN];   // 64 MB, [b][c][rank]
__device__ __align__(256) float d_h1[(size_t)BB * HH * NN];   // 64 MB
__device__ __align__(256) float d_agg0[BB * SS * HH];
__device__ __align__(256) float d_agg1[BB * SS * HH];
__device__ __align__(256) float d_agg2[BB * SS * HH];
__device__ __align__(256) float d_aggW[BB * SS * HH];         // bias + agg@W_bot, per layer
__device__ int            d_perm[BB * NN];
__device__ int            d_cs[BB * NN];                      // sorted cluster ids

// ---------------- f32x2 packed fp32 helpers (bit-exact IEEE fma on both halves) ----------------
__device__ __forceinline__ u64 pack2f(float lo, float hi) {
    u64 r; asm("mov.b64 %0, {%1,%2};" : "=l"(r) : "f"(lo), "f"(hi)); return r;
}
__device__ __forceinline__ void unpack2f(u64 v, float& lo, float& hi) {
    asm("mov.b64 {%0,%1}, %2;" : "=f"(lo), "=f"(hi) : "l"(v));
}
__device__ __forceinline__ u64 fma2f(u64 a, u64 b, u64 c) {
    u64 d; asm("fma.rn.f32x2 %0, %1, %2, %3;" : "=l"(d) : "l"(a), "l"(b), "l"(c)); return d;
}

// ---------------- cp.async helpers ----------------
__device__ __forceinline__ void cp_async16(uint32_t dst_smem, const void* src) {
    asm volatile("cp.async.ca.shared.global [%0], [%1], 16;" :: "r"(dst_smem), "l"(src));
}
__device__ __forceinline__ void cp_commit() {
    asm volatile("cp.async.commit_group;" ::: "memory");
}
template <int N>
__device__ __forceinline__ void cp_wait() {
    asm volatile("cp.async.wait_group %0;" :: "n"(N) : "memory");
}

// ---------------- prep: dtype-detect + per-batch counting sort + agg zero ----------------
__global__ void prep_kernel(const void* __restrict__ cl) {
    __shared__ int cnt[SS];
    __shared__ int cur[SS];
    __shared__ int isll;
    int b = blockIdx.x, tid = threadIdx.x;
    if (tid == 0) {
        const long long* p = (const long long*)cl;
        int ok = 1;
        for (int i = 0; i < 16; i++) { long long v = p[i]; if (v < 0 || v >= SS) ok = 0; }
        isll = ok;
    }
    if (tid < SS) cnt[tid] = 0;
    float* a0 = d_agg0 + b * SS * HH;
    float* a1 = d_agg1 + b * SS * HH;
    float* a2 = d_agg2 + b * SS * HH;
    for (int i = tid; i < SS * HH; i += blockDim.x) { a0[i] = 0.f; a1[i] = 0.f; a2[i] = 0.f; }
    __syncthreads();
    const long long* p64 = (const long long*)cl;
    const int*       p32 = (const int*)cl;
    int l = isll;
    for (int n = tid; n < NN; n += blockDim.x) {
        int s = l ? (int)p64[(size_t)b * NN + n] : p32[(size_t)b * NN + n];
        atomicAdd(&cnt[s], 1);
    }
    __syncthreads();
    if (tid == 0) {
        int run = 0;
        for (int s = 0; s < SS; s++) { int c = cnt[s]; cur[s] = run; run += c; }
    }
    __syncthreads();
    for (int n = tid; n < NN; n += blockDim.x) {
        int s = l ? (int)p64[(size_t)b * NN + n] : p32[(size_t)b * NN + n];
        int r = atomicAdd(&cur[s], 1);
        d_perm[b * NN + r] = n;
        d_cs[b * NN + r]   = s;
    }
}

// ---------------- layer 0: gather x via perm, 8->64 matvec, LN/relu, write h0 + agg0 ----------------
__global__ __launch_bounds__(256) void layer0_kernel(const float* __restrict__ x,
                                                     const float* __restrict__ W0,
                                                     const float* __restrict__ b0,
                                                     const float* __restrict__ g0,
                                                     const float* __restrict__ be0) {
    __shared__ __align__(16) float Wsm[8 * HH];
    __shared__ float bsm[HH], gsm[HH], besm[HH];
    int tid = threadIdx.x, b = blockIdx.y;
    int rank = blockIdx.x * 256 + tid;
    for (int i = tid; i < 8 * HH; i += 256) Wsm[i] = W0[i];
    if (tid < HH) { bsm[tid] = b0[tid]; gsm[tid] = g0[tid]; besm[tid] = be0[tid]; }
    __syncthreads();
    int n = d_perm[b * NN + rank];
    int s = d_cs[b * NN + rank];
    const float4* xp = (const float4*)(x + ((size_t)b * NN + n) * 8);
    float4 xa = xp[0], xb = xp[1];
    float xv[8] = {xa.x, xa.y, xa.z, xa.w, xb.x, xb.y, xb.z, xb.w};
    float acc[HH];
#pragma unroll
    for (int i = 0; i < HH; i++) acc[i] = bsm[i];
#pragma unroll
    for (int k = 0; k < 8; k++) {
        float h = xv[k];
        const float* wr = Wsm + k * HH;
#pragma unroll
        for (int i = 0; i < HH; i++) acc[i] = fmaf(h, wr[i], acc[i]);
    }
    float sum = 0.f;
#pragma unroll
    for (int i = 0; i < HH; i++) sum += acc[i];
    float mu = sum * (1.0f / 64.0f);
    float ssq = 0.f;
#pragma unroll
    for (int i = 0; i < HH; i++) { float d = acc[i] - mu; ssq = fmaf(d, d, ssq); }
    float rs = rsqrtf(ssq * (1.0f / 64.0f) + 1e-5f);
    float* houtp = d_h0 + ((size_t)b * HH) * NN + rank;
#pragma unroll
    for (int i = 0; i < HH; i++) {
        float r = fmaxf(fmaf((acc[i] - mu) * rs, gsm[i], besm[i]), 0.0f);
        houtp[(size_t)i * NN] = r;
        acc[i] = r;
    }
    unsigned match = __match_any_sync(0xffffffffu, s);
    bool leader = ((threadIdx.x & 31) == (__ffs(match) - 1));
    float* agg = d_agg0 + (((b << 6) + s) << 6);
#pragma unroll
    for (int i = 0; i < HH; i++) {
        int m = __reduce_max_sync(match, __float_as_int(acc[i]));
        if (leader) atomicMax((int*)(agg + i), m);
    }
}

// ---------------- tiny GEMM: aggW[b] = bias + agg[b] @ W_bot (thread-per-output) ----------------
__global__ __launch_bounds__(256) void smallmm_kernel(const float* __restrict__ Wfull,
                                                      const float* __restrict__ bias, int stage) {
    __shared__ float Wsm[HH * HH];
    __shared__ float bsm[HH];
    const float* Wbot = Wfull + 64 * HH;
    const float* agg = (stage == 0) ? d_agg0 : d_agg1;
    int tid = threadIdx.x;
    int gid = blockIdx.x * 256 + tid;
    for (int i = tid; i < HH * HH; i += 256) Wsm[i] = Wbot[i];
    if (tid < HH) bsm[tid] = bias[tid];
    __syncthreads();
    int c = gid & 63;
    int row = gid >> 6;
    const float* A = agg + (row << 6);
    float a = bsm[c];
#pragma unroll 8
    for (int k = 0; k < HH; k++) a = fmaf(A[k], Wsm[(k << 6) + c], a);
    d_aggW[gid] = a;
}

// ---------------- layers 1/2: P=8 x C=8 register-blocked GEMM, 128-thr blocks, cp.async ----
// block 128 threads = 16 point-groups x 8 channel-groups; tile = 128 points x 64 channels.
// W swizzled (float4 j of row k at slot ((j&1)<<3)|(j>>1)); read back as ulonglong2 so the
// FFMA2 W operands come straight out of LDS.128 register pairs.
template <int STAGE>
__global__ __launch_bounds__(128, 4) void layer12_kernel(const float* __restrict__ W,
                                                         const float* __restrict__ g,
                                                         const float* __restrict__ be) {
    __shared__ __align__(16) float wsm[HH * HH];        // 16 KB, swizzled [k][slot]
    __shared__ __align__(16) float hsm[2][16 * 128];    // 2 x 8 KB chunk, [r][point]
    __shared__ float gsm[HH], besm[HH];
    int tid = threadIdx.x, b = blockIdx.y;
    int pg = tid >> 3;          // 0..15
    int cg = tid & 7;           // 0..7
    int pbase = blockIdx.x * 128;
    int p0 = pbase + pg * 8;    // first of this thread's 8 points

    // stage W with swizzle (1024 float4 over 128 threads)
    for (int i = tid; i < (HH * HH) / 4; i += 128) {
        int k = i >> 4, j = i & 15;
        int slot = ((j & 1) << 3) | (j >> 1);
        ((float4*)wsm)[k * 16 + slot] = ((const float4*)W)[i];
    }
    if (tid < HH) { gsm[tid] = g[tid]; besm[tid] = be[tid]; }

    const float* hbase = ((STAGE == 1) ? d_h0 : d_h1) + ((size_t)b * HH) * NN + pbase;
    uint32_t hsm_base = (uint32_t)__cvta_generic_to_shared(&hsm[0][0]);

    // async-stage chunk kc (16 k-rows x 128 points) into buffer kc&1
    auto stage_chunk = [&](int kc) {
        uint32_t dst = hsm_base + (kc & 1) * (16 * 128 * 4);
#pragma unroll
        for (int it = 0; it < 4; it++) {
            int i = it * 128 + tid;           // 0..511
            int r = i >> 5, c4 = i & 31;
            cp_async16(dst + (r * 128 + c4 * 4) * 4,
                       hbase + (size_t)(kc * 16 + r) * NN + c4 * 4);
        }
        cp_commit();
    };

    // per-point cluster ids (8 consecutive ints = 2 int4)
    int sj[8];
    {
        const int4* cp = (const int4*)(d_cs + b * NN + p0);
        int4 c0 = cp[0], c1 = cp[1];
        sj[0] = c0.x; sj[1] = c0.y; sj[2] = c0.z; sj[3] = c0.w;
        sj[4] = c1.x; sj[5] = c1.y; sj[6] = c1.z; sj[7] = c1.w;
    }

    stage_chunk(0);

    // acc init from aggW[s] (bias folded in) — overlaps with the first async copy
    u64 acc2[8][4];
#pragma unroll
    for (int j = 0; j < 8; j++) {
        const float4* aw = (const float4*)(d_aggW + (((size_t)b * SS + sj[j]) << 6) + cg * 8);
        float4 a0 = aw[0], a1 = aw[1];
        acc2[j][0] = pack2f(a0.x, a0.y);
        acc2[j][1] = pack2f(a0.z, a0.w);
        acc2[j][2] = pack2f(a1.x, a1.y);
        acc2[j][3] = pack2f(a1.z, a1.w);
    }

    for (int kc = 0; kc < 4; kc++) {
        if (kc < 3) stage_chunk(kc + 1);
        if (kc < 3) cp_wait<1>(); else cp_wait<0>();
        __syncthreads();
        const float* hbuf = hsm[kc & 1];
#pragma unroll
        for (int r = 0; r < 16; r++) {
            int k = kc * 16 + r;
            const float4* hp4 = (const float4*)(hbuf + r * 128 + pg * 8);
            float4 hA = hp4[0], hB = hp4[1];
            const ulonglong2* wrow = (const ulonglong2*)(wsm + k * HH);
            ulonglong2 wv0 = wrow[cg];        // channels 8cg..8cg+3 (slots cg)
            ulonglong2 wv1 = wrow[8 + cg];    // channels 8cg+4..8cg+7 (slots 8+cg)
            float hv[8] = {hA.x, hA.y, hA.z, hA.w, hB.x, hB.y, hB.z, hB.w};
#pragma unroll
            for (int j = 0; j < 8; j++) {
                u64 hs = pack2f(hv[j], hv[j]);
                acc2[j][0] = fma2f(hs, wv0.x, acc2[j][0]);
                acc2[j][1] = fma2f(hs, wv0.y, acc2[j][1]);
                acc2[j][2] = fma2f(hs, wv1.x, acc2[j][2]);
                acc2[j][3] = fma2f(hs, wv1.y, acc2[j][3]);
            }
        }
        __syncthreads();
    }

    float acc[8][8];
#pragma unroll
    for (int j = 0; j < 8; j++)
#pragma unroll
        for (int i = 0; i < 4; i++) unpack2f(acc2[j][i], acc[j][2 * i], acc[j][2 * i + 1]);

    // LN mean/var: butterfly over the 8 channel-group lanes (lane bits 0..2)
    const unsigned fm = 0xffffffffu;
    float s1[8];
#pragma unroll
    for (int j = 0; j < 8; j++) {
        float t = 0.f;
#pragma unroll
        for (int i = 0; i < 8; i++) t += acc[j][i];
        s1[j] = t;
    }
#pragma unroll
    for (int d = 1; d < 8; d <<= 1)
#pragma unroll
        for (int j = 0; j < 8; j++) s1[j] += __shfl_xor_sync(fm, s1[j], d);
    float mu[8];
#pragma unroll
    for (int j = 0; j < 8; j++) mu[j] = s1[j] * (1.0f / 64.0f);
    float s2[8];
#pragma unroll
    for (int j = 0; j < 8; j++) {
        float t = 0.f;
#pragma unroll
        for (int i = 0; i < 8; i++) { float d = acc[j][i] - mu[j]; t = fmaf(d, d, t); }
        s2[j] = t;
    }
#pragma unroll
    for (int d = 1; d < 8; d <<= 1)
#pragma unroll
        for (int j = 0; j < 8; j++) s2[j] += __shfl_xor_sync(fm, s2[j], d);
    float rs[8];
#pragma unroll
    for (int j = 0; j < 8; j++) rs[j] = rsqrtf(s2[j] * (1.0f / 64.0f) + 1e-5f);

    // normalize + relu
#pragma unroll
    for (int j = 0; j < 8; j++)
#pragma unroll
        for (int i = 0; i < 8; i++) {
            int c = cg * 8 + i;
            acc[j][i] = fmaxf(fmaf((acc[j][i] - mu[j]) * rs[j], gsm[c], besm[c]), 0.0f);
        }

    // write h (STAGE 1 only): two float4 per channel covering the 8 consecutive points
    if (STAGE == 1) {
        float* hout = d_h1 + ((size_t)b * HH) * NN + p0;
#pragma unroll
        for (int i = 0; i < 8; i++) {
            int c = cg * 8 + i;
            float4 v0 = make_float4(acc[0][i], acc[1][i], acc[2][i], acc[3][i]);
            float4 v1 = make_float4(acc[4][i], acc[5][i], acc[6][i], acc[7][i]);
            *(float4*)(hout + (size_t)c * NN)     = v0;
            *(float4*)(hout + (size_t)c * NN + 4) = v1;
        }
    }

    // segmented max over this thread's 8 consecutive (sorted) points: run-flush with atomics
    float* agg = ((STAGE == 1) ? d_agg1 : d_agg2) + ((size_t)b << 12);
    float run[8];
#pragma unroll
    for (int i = 0; i < 8; i++) run[i] = acc[0][i];
    int sprev = sj[0];
#pragma unroll
    for (int j = 1; j < 8; j++) {
        if (sj[j] == sprev) {
#pragma unroll
            for (int i = 0; i < 8; i++) run[i] = fmaxf(run[i], acc[j][i]);
        } else {
            float* dst = agg + (sprev << 6) + cg * 8;
#pragma unroll
            for (int i = 0; i < 8; i++) atomicMax((int*)(dst + i), __float_as_int(run[i]));
            sprev = sj[j];
#pragma unroll
            for (int i = 0; i < 8; i++) run[i] = acc[j][i];
        }
    }
    {
        float* dst = agg + (sprev << 6) + cg * 8;
#pragma unroll
        for (int i = 0; i < 8; i++) atomicMax((int*)(dst + i), __float_as_int(run[i]));
    }
}

// ---------------- final: out[b,s,c]=out[b,s,64+c]=agg2[b,s,c]/max(||col||, eps) ----------------
__global__ void final_kernel(float* __restrict__ out) {
    int b = blockIdx.x;
    int c = threadIdx.x;
    const float* a = d_agg2 + b * SS * HH;
    float ss = 0.f;
#pragma unroll 8
    for (int s = 0; s < SS; s++) { float v = a[s * HH + c]; ss = fmaf(v, v, ss); }
    float inv = 1.0f / fmaxf(sqrtf(ss), 1e-12f);
    for (int s = 0; s < SS; s++) {
        float o = a[s * HH + c] * inv;
        out[((size_t)(b * SS + s)) * 128 + c]      = o;
        out[((size_t)(b * SS + s)) * 128 + 64 + c] = o;
    }
}

// ---------------- launch ----------------
extern "C" void kernel_launch(void* const* d_in, const int* in_sizes, int n_in,
                              void* d_out, int out_size) {
    const float* x  = (const float*)d_in[0];
    const void*  cl = d_in[1];
    const float* W0 = (const float*)d_in[2];
    const float* b0 = (const float*)d_in[3];
    const float* g0 = (const float*)d_in[4];
    const float* e0 = (const float*)d_in[5];
    const float* W1 = (const float*)d_in[6];
    const float* b1 = (const float*)d_in[7];
    const float* g1 = (const float*)d_in[8];
    const float* e1 = (const float*)d_in[9];
    const float* W2 = (const float*)d_in[10];
    const float* b2 = (const float*)d_in[11];
    const float* g2 = (const float*)d_in[12];
    const float* e2 = (const float*)d_in[13];
    float* out = (float*)d_out;

    const int SMALLMM_BLOCKS = (BB * SS * HH) / 256;               // 2048

    prep_kernel<<<BB, 256>>>(cl);                                  // 1
    layer0_kernel<<<dim3(NN / 256, BB), 256>>>(x, W0, b0, g0, e0); // 2
    smallmm_kernel<<<SMALLMM_BLOCKS, 256>>>(W1, b1, 0);            // 3
    layer12_kernel<1><<<dim3(NN / 128, BB), 128>>>(W1, g1, e1);    // 4
    smallmm_kernel<<<SMALLMM_BLOCKS, 256>>>(W2, b2, 1);            // 5
    layer12_kernel<2><<<dim3(NN / 128, BB), 128>>>(W2, g2, e2);    // 6  <- ncu -s5 -c1
    final_kernel<<<BB, 64>>>(out);                                 // 7
}